// round 2
// baseline (speedup 1.0000x reference)
#include <cuda_runtime.h>

// Problem constants
#define HDIM   512
#define BATCH  2
#define SEQ    128
#define DSRC   768
#define NTOK   (BATCH * SEQ)   // 256
#define NITER  30

// SCALE/REG * log2(e) = 5000 * 1.4426950408889634
#define NEGC  (-7213.4752044448170f)
// -log2(H) = -log2(512)
#define LOGMARG2 (-9.0f)

// Scratch (static device globals; no runtime allocation allowed)
__device__ float g_src[NTOK * HDIM];            // 512 KB
__device__ float g_sumP[BATCH * HDIM * HDIM];   // 2 MB

__device__ __forceinline__ float ex2(float x) {
    float y; asm("ex2.approx.f32 %0, %1;" : "=f"(y) : "f"(x)); return y;
}
__device__ __forceinline__ float lg2(float x) {
    float y; asm("lg2.approx.f32 %0, %1;" : "=f"(y) : "f"(x)); return y;
}

// ---------------------------------------------------------------------------
// Stage 0: zero the plan accumulator (must happen every launch; graph replays)
// ---------------------------------------------------------------------------
__global__ void zero_kernel() {
    int i = blockIdx.x * blockDim.x + threadIdx.x;
    if (i < BATCH * HDIM * HDIM) g_sumP[i] = 0.0f;
}

// ---------------------------------------------------------------------------
// Stage 1: src[tok, h] = sum_d X[tok, d] * W[h, d] + b[h]
// One CTA per token, thread h. W rows are L2-resident (1.5 MB).
// ---------------------------------------------------------------------------
__global__ void __launch_bounds__(HDIM) src_kernel(
    const float* __restrict__ X, const float* __restrict__ W,
    const float* __restrict__ b)
{
    const int tok = blockIdx.x;
    __shared__ __align__(16) float xs[DSRC];
    for (int d = threadIdx.x; d < DSRC; d += blockDim.x)
        xs[d] = X[tok * DSRC + d];
    __syncthreads();

    const int h = threadIdx.x;
    const float4* wr = reinterpret_cast<const float4*>(W + (size_t)h * DSRC);
    const float4* xr = reinterpret_cast<const float4*>(xs);
    float acc = 0.0f;
#pragma unroll 8
    for (int q = 0; q < DSRC / 4; q++) {
        float4 w4 = wr[q];
        float4 x4 = xr[q];
        acc = fmaf(w4.x, x4.x, acc);
        acc = fmaf(w4.y, x4.y, acc);
        acc = fmaf(w4.z, x4.z, acc);
        acc = fmaf(w4.w, x4.w, acc);
    }
    g_src[tok * HDIM + h] = acc + b[h];
}

// ---------------------------------------------------------------------------
// Stage 2: per-token log-domain (base-2) Sinkhorn, 30 iterations, then
// accumulate the transport plan into the per-batch sum buffer.
//
// One CTA per token, 512 threads = 16 warps. Each warp owns rows
// j = warp + 16*r (r = 0..31); each lane owns columns i = lane + 32*k
// (k = 0..15). logK2[j,i] = -7213.475 * (s_i - t_j)^2 recomputed on the fly
// (3 FMA-pipe ops), w kept in 16 registers for the two-phase LSE.
// ---------------------------------------------------------------------------
__global__ void __launch_bounds__(512, 2) sinkhorn_kernel(
    const float* __restrict__ Y)
{
    const int tok  = blockIdx.x;
    const int bat  = tok >> 7;   // tok / SEQ
    const int tid  = threadIdx.x;
    const int lane = tid & 31;
    const int warp = tid >> 5;

    __shared__ float sv[HDIM];   // source values (src row)
    __shared__ float tv[HDIM];   // target values (Y row)
    __shared__ float uu[HDIM];   // u (base-2)
    __shared__ float vv[HDIM];   // v (base-2)

    for (int i = tid; i < HDIM; i += 512) {
        sv[i] = g_src[tok * HDIM + i];
        tv[i] = Y[tok * HDIM + i];
        uu[i] = 0.0f;
        vv[i] = 0.0f;
    }
    __syncthreads();

    // Cache this lane's fixed column slice of s (constant for whole token)
    float sreg[16];
#pragma unroll
    for (int k = 0; k < 16; k++) sreg[k] = sv[lane + 32 * k];

    for (int it = 0; it < NITER; it++) {
        // ---- u-pass: u[j] = -9 - lse2_i( logK2[j,i] + v[i] ) ----
#pragma unroll 1
        for (int r = 0; r < 32; r++) {
            const int j = warp + 16 * r;
            const float tj = tv[j];
            float w[16];
#pragma unroll
            for (int k = 0; k < 16; k++) {
                float d = sreg[k] - tj;
                w[k] = fmaf(d * d, NEGC, vv[lane + 32 * k]);
            }
            float m0 = w[0], m1 = w[1];
#pragma unroll
            for (int k = 2; k < 16; k += 2) {
                m0 = fmaxf(m0, w[k]);
                m1 = fmaxf(m1, w[k + 1]);
            }
            float m = fmaxf(m0, m1);
#pragma unroll
            for (int o = 16; o; o >>= 1)
                m = fmaxf(m, __shfl_xor_sync(0xffffffffu, m, o));
            float a0 = 0.0f, a1 = 0.0f;
#pragma unroll
            for (int k = 0; k < 16; k += 2) {
                a0 += ex2(w[k] - m);
                a1 += ex2(w[k + 1] - m);
            }
            float a = a0 + a1;
#pragma unroll
            for (int o = 16; o; o >>= 1)
                a += __shfl_xor_sync(0xffffffffu, a, o);
            if (lane == 0) uu[j] = LOGMARG2 - (m + lg2(a));
        }
        __syncthreads();

        // ---- v-pass: v[i] = -9 - lse2_j( logK2[j,i] + u[j] ) ----
#pragma unroll 1
        for (int r = 0; r < 32; r++) {
            const int i = warp + 16 * r;
            const float si = sv[i];
            float w[16];
#pragma unroll
            for (int k = 0; k < 16; k++) {
                float d = si - tv[lane + 32 * k];
                w[k] = fmaf(d * d, NEGC, uu[lane + 32 * k]);
            }
            float m0 = w[0], m1 = w[1];
#pragma unroll
            for (int k = 2; k < 16; k += 2) {
                m0 = fmaxf(m0, w[k]);
                m1 = fmaxf(m1, w[k + 1]);
            }
            float m = fmaxf(m0, m1);
#pragma unroll
            for (int o = 16; o; o >>= 1)
                m = fmaxf(m, __shfl_xor_sync(0xffffffffu, m, o));
            float a0 = 0.0f, a1 = 0.0f;
#pragma unroll
            for (int k = 0; k < 16; k += 2) {
                a0 += ex2(w[k] - m);
                a1 += ex2(w[k + 1] - m);
            }
            float a = a0 + a1;
#pragma unroll
            for (int o = 16; o; o >>= 1)
                a += __shfl_xor_sync(0xffffffffu, a, o);
            if (lane == 0) vv[i] = LOGMARG2 - (m + lg2(a));
        }
        __syncthreads();
    }

    // ---- Plan: P[j,i] = 2^( logK2[j,i] + u[j] + v[i] ); accumulate per batch
    float* dst = g_sumP + (size_t)bat * HDIM * HDIM;
#pragma unroll 1
    for (int r = 0; r < 32; r++) {
        const int j  = warp + 16 * r;
        const float tj = tv[j];
        const float uj = uu[j];
#pragma unroll
        for (int k = 0; k < 16; k++) {
            float d = sreg[k] - tj;
            float p = ex2(fmaf(d * d, NEGC, vv[lane + 32 * k]) + uj);
            atomicAdd(dst + j * HDIM + lane + 32 * k, p);
        }
    }
}

// ---------------------------------------------------------------------------
// Stage 3: out[tok, k] = sum_h src[tok, h] * ( sumP[b,h,k] * (H*SCALE/S)
//                                              + delta[h,k] )
// (H*SCALE/S = 512*500/128 = 2000: converts plan-sum to mean*H*SCALE)
// ---------------------------------------------------------------------------
__global__ void __launch_bounds__(HDIM) out_kernel(
    const float* __restrict__ delta, float* __restrict__ out)
{
    const int tok = blockIdx.x;
    const int bat = tok >> 7;
    __shared__ float sr[HDIM];
    for (int i = threadIdx.x; i < HDIM; i += blockDim.x)
        sr[i] = g_src[tok * HDIM + i];
    __syncthreads();

    const int k = threadIdx.x;
    const float* P = g_sumP + (size_t)bat * HDIM * HDIM;
    const float sc = 2000.0f;  // 512*500/128
    float acc = 0.0f;
#pragma unroll 8
    for (int h = 0; h < HDIM; h++) {
        acc = fmaf(sr[h], fmaf(P[h * HDIM + k], sc, delta[h * HDIM + k]), acc);
    }
    out[tok * HDIM + k] = acc;
}

// ---------------------------------------------------------------------------
extern "C" void kernel_launch(void* const* d_in, const int* in_sizes, int n_in,
                              void* d_out, int out_size)
{
    const float* X     = (const float*)d_in[0];  // (2,128,768)
    const float* Y     = (const float*)d_in[1];  // (2,128,512)
    const float* W     = (const float*)d_in[2];  // (512,768)
    const float* b     = (const float*)d_in[3];  // (512)
    const float* delta = (const float*)d_in[4];  // (512,512)
    float* out = (float*)d_out;                  // (2,128,512)

    zero_kernel<<<(BATCH * HDIM * HDIM + 511) / 512, 512>>>();
    src_kernel<<<NTOK, HDIM>>>(X, W, b);
    sinkhorn_kernel<<<NTOK, 512>>>(Y);
    out_kernel<<<NTOK, HDIM>>>(delta, out);
}

// round 3
// speedup vs baseline: 1.1221x; 1.1221x over previous
#include <cuda_runtime.h>

// Problem constants
#define HDIM   512
#define BATCH  2
#define SEQ    128
#define DSRC   768
#define NTOK   (BATCH * SEQ)   // 256
#define NITER  30

// -(SCALE/REG) * log2(e) = -5000 * 1.4426950408889634
#define NEGC  (-7213.4752044448170f)
// -log2(H)
#define LOGMARG2 (-9.0f)

typedef unsigned long long ull;

// Scratch (static device globals; no runtime allocation allowed)
__device__ float g_src[NTOK * HDIM];            // 512 KB
__device__ float g_sumP[BATCH * HDIM * HDIM];   // 2 MB

// ---------------------------------------------------------------------------
// PTX helpers: fp32 MUFU + Blackwell packed f32x2
// ---------------------------------------------------------------------------
__device__ __forceinline__ float ex2(float x) {
    float y; asm("ex2.approx.f32 %0, %1;" : "=f"(y) : "f"(x)); return y;
}
__device__ __forceinline__ float lg2(float x) {
    float y; asm("lg2.approx.f32 %0, %1;" : "=f"(y) : "f"(x)); return y;
}
__device__ __forceinline__ ull pack2(float lo, float hi) {
    ull r; asm("mov.b64 %0, {%1, %2};" : "=l"(r) : "f"(lo), "f"(hi)); return r;
}
__device__ __forceinline__ void unpack2(ull v, float& lo, float& hi) {
    asm("mov.b64 {%0, %1}, %2;" : "=f"(lo), "=f"(hi) : "l"(v));
}
__device__ __forceinline__ ull addx2(ull a, ull b) {
    ull r; asm("add.rn.f32x2 %0, %1, %2;" : "=l"(r) : "l"(a), "l"(b)); return r;
}
__device__ __forceinline__ ull mulx2(ull a, ull b) {
    ull r; asm("mul.rn.f32x2 %0, %1, %2;" : "=l"(r) : "l"(a), "l"(b)); return r;
}
__device__ __forceinline__ ull fmax2p(ull a, ull b, ull c) {
    ull r; asm("fma.rn.f32x2 %0, %1, %2, %3;" : "=l"(r) : "l"(a), "l"(b), "l"(c)); return r;
}

// ---------------------------------------------------------------------------
// Stage 0: zero the plan accumulator (graph replays -> must run every launch)
// ---------------------------------------------------------------------------
__global__ void zero_kernel() {
    int i = blockIdx.x * blockDim.x + threadIdx.x;
    float4 z = make_float4(0.f, 0.f, 0.f, 0.f);
    reinterpret_cast<float4*>(g_sumP)[i] = z;   // grid sized exactly
}

// ---------------------------------------------------------------------------
// Stage 1: src[tok, h] = X[tok] . W[h] + b[h]   (4 tokens per CTA)
// ---------------------------------------------------------------------------
#define TPG 4
__global__ void __launch_bounds__(HDIM) src_kernel(
    const float* __restrict__ X, const float* __restrict__ W,
    const float* __restrict__ b)
{
    const int tok0 = blockIdx.x * TPG;
    __shared__ __align__(16) float xs[TPG][DSRC];   // 12 KB
    for (int idx = threadIdx.x; idx < TPG * DSRC; idx += HDIM)
        xs[idx / DSRC][idx % DSRC] = X[tok0 * DSRC + idx];
    __syncthreads();

    const int h = threadIdx.x;
    const float4* wr = reinterpret_cast<const float4*>(W + (size_t)h * DSRC);
    float acc0 = 0.f, acc1 = 0.f, acc2 = 0.f, acc3 = 0.f;
#pragma unroll 4
    for (int q = 0; q < DSRC / 4; q++) {
        float4 w4 = wr[q];
        float4 x0 = reinterpret_cast<const float4*>(xs[0])[q];
        float4 x1 = reinterpret_cast<const float4*>(xs[1])[q];
        float4 x2 = reinterpret_cast<const float4*>(xs[2])[q];
        float4 x3 = reinterpret_cast<const float4*>(xs[3])[q];
        acc0 = fmaf(w4.x, x0.x, acc0); acc0 = fmaf(w4.y, x0.y, acc0);
        acc0 = fmaf(w4.z, x0.z, acc0); acc0 = fmaf(w4.w, x0.w, acc0);
        acc1 = fmaf(w4.x, x1.x, acc1); acc1 = fmaf(w4.y, x1.y, acc1);
        acc1 = fmaf(w4.z, x1.z, acc1); acc1 = fmaf(w4.w, x1.w, acc1);
        acc2 = fmaf(w4.x, x2.x, acc2); acc2 = fmaf(w4.y, x2.y, acc2);
        acc2 = fmaf(w4.z, x2.z, acc2); acc2 = fmaf(w4.w, x2.w, acc2);
        acc3 = fmaf(w4.x, x3.x, acc3); acc3 = fmaf(w4.y, x3.y, acc3);
        acc3 = fmaf(w4.z, x3.z, acc3); acc3 = fmaf(w4.w, x3.w, acc3);
    }
    float bh = b[h];
    g_src[(tok0 + 0) * HDIM + h] = acc0 + bh;
    g_src[(tok0 + 1) * HDIM + h] = acc1 + bh;
    g_src[(tok0 + 2) * HDIM + h] = acc2 + bh;
    g_src[(tok0 + 3) * HDIM + h] = acc3 + bh;
}

// ---------------------------------------------------------------------------
// Warp-collective base-2 LSE of one row:
//   lse = log2( sum_i 2^( NEGC*(col_i - rowval)^2 + dual_i ) )
// colv/dualv: 8 packed f32x2 regs covering columns (lane+32k, lane+32k+256).
// All lanes return the lse value.
// ---------------------------------------------------------------------------
__device__ __forceinline__ float warp_lse(const ull* colv, const ull* dualv,
                                          float rowval)
{
    const ull negc2 = pack2(NEGC, NEGC);
    const ull nr2 = pack2(-rowval, -rowval);
    ull w[8];
    float m0 = -3.402823466e+38f, m1 = -3.402823466e+38f;
#pragma unroll
    for (int k = 0; k < 8; k++) {
        ull d = addx2(colv[k], nr2);          // s - t
        ull q = mulx2(d, d);                  // (s-t)^2
        w[k] = fmax2p(q, negc2, dualv[k]);    // NEGC*(s-t)^2 + dual
        float wl, wh; unpack2(w[k], wl, wh);
        m0 = fmaxf(m0, wl); m1 = fmaxf(m1, wh);
    }
    float m = fmaxf(m0, m1);
#pragma unroll
    for (int o = 16; o; o >>= 1)
        m = fmaxf(m, __shfl_xor_sync(0xffffffffu, m, o));
    const ull nm2 = pack2(-m, -m);
    ull acc2 = 0ull;  // packed (0.0f, 0.0f)
#pragma unroll
    for (int k = 0; k < 8; k++) {
        ull e = addx2(w[k], nm2);
        float el, eh; unpack2(e, el, eh);
        acc2 = addx2(acc2, pack2(ex2(el), ex2(eh)));
    }
    float al, ah; unpack2(acc2, al, ah);
    float a = al + ah;
#pragma unroll
    for (int o = 16; o; o >>= 1)
        a += __shfl_xor_sync(0xffffffffu, a, o);
    return m + lg2(a);
}

// ---------------------------------------------------------------------------
// Stage 2: per-token log-domain (base-2) Sinkhorn + plan accumulation.
// One CTA per token, 512 threads = 16 warps. Warp handles rows j = warp+16r.
// SMEM layout: packed float2 arrays, element m pairs indices (m, m+256).
// ---------------------------------------------------------------------------
__global__ void __launch_bounds__(512, 2) sinkhorn_kernel(
    const float* __restrict__ Y)
{
    const int tok  = blockIdx.x;
    const int bat  = tok >> 7;
    const int tid  = threadIdx.x;
    const int lane = tid & 31;
    const int warp = tid >> 5;

    __shared__ __align__(8) float2 sp[256];   // (s[m], s[m+256])
    __shared__ __align__(8) float2 tp[256];   // (t[m], t[m+256])
    __shared__ __align__(8) float2 up[256];   // (u[m], u[m+256])
    __shared__ __align__(8) float2 vp[256];   // (v[m], v[m+256])

    if (tid < 256) {
        sp[tid] = make_float2(g_src[tok * HDIM + tid], g_src[tok * HDIM + tid + 256]);
        tp[tid] = make_float2(Y[tok * HDIM + tid],     Y[tok * HDIM + tid + 256]);
        up[tid] = make_float2(0.f, 0.f);
        vp[tid] = make_float2(0.f, 0.f);
    }
    __syncthreads();

    const float* tp_s = reinterpret_cast<const float*>(tp);
    const float* sp_s = reinterpret_cast<const float*>(sp);
    float* up_s = reinterpret_cast<float*>(up);
    float* vp_s = reinterpret_cast<float*>(vp);
    const ull* sp_p = reinterpret_cast<const ull*>(sp);
    const ull* tp_p = reinterpret_cast<const ull*>(tp);
    const ull* up_p = reinterpret_cast<const ull*>(up);
    const ull* vp_p = reinterpret_cast<const ull*>(vp);

    for (int it = 0; it < NITER; it++) {
        // ---- u-pass: u[j] = -9 - lse_i( NEGC*(s_i - t_j)^2 + v_i ) ----
        {
            ull c2[8], d2[8];
#pragma unroll
            for (int k = 0; k < 8; k++) {
                c2[k] = sp_p[lane + 32 * k];
                d2[k] = vp_p[lane + 32 * k];
            }
#pragma unroll 1
            for (int r = 0; r < 32; r++) {
                const int j = warp + 16 * r;
                const float tj = tp_s[((j & 255) << 1) | (j >> 8)];
                float lse = warp_lse(c2, d2, tj);
                if (lane == 0)
                    up_s[((j & 255) << 1) | (j >> 8)] = LOGMARG2 - lse;
            }
        }
        __syncthreads();

        // ---- v-pass: v[i] = -9 - lse_j( NEGC*(s_i - t_j)^2 + u_j ) ----
        {
            ull c2[8], d2[8];
#pragma unroll
            for (int k = 0; k < 8; k++) {
                c2[k] = tp_p[lane + 32 * k];
                d2[k] = up_p[lane + 32 * k];
            }
#pragma unroll 1
            for (int r = 0; r < 32; r++) {
                const int i = warp + 16 * r;
                const float si = sp_s[((i & 255) << 1) | (i >> 8)];
                float lse = warp_lse(c2, d2, si);
                if (lane == 0)
                    vp_s[((i & 255) << 1) | (i >> 8)] = LOGMARG2 - lse;
            }
        }
        __syncthreads();
    }

    // ---- Plan: P[j,i] = 2^( NEGC*(s_i - t_j)^2 + u_j + v_i ), accumulate ----
    {
        float* dst = g_sumP + (size_t)bat * HDIM * HDIM;
        const ull negc2 = pack2(NEGC, NEGC);
        ull c2[8], d2[8];
#pragma unroll
        for (int k = 0; k < 8; k++) {
            c2[k] = sp_p[lane + 32 * k];
            d2[k] = vp_p[lane + 32 * k];
        }
#pragma unroll 1
        for (int r = 0; r < 32; r++) {
            const int j = warp + 16 * r;
            const float tj = tp_s[((j & 255) << 1) | (j >> 8)];
            const float uj = up_s[((j & 255) << 1) | (j >> 8)];
            const ull nt2 = pack2(-tj, -tj);
            const ull uj2 = pack2(uj, uj);
            float* rowdst = dst + j * HDIM + lane;
#pragma unroll
            for (int k = 0; k < 8; k++) {
                ull d = addx2(c2[k], nt2);
                ull q = mulx2(d, d);
                ull w = fmax2p(q, negc2, d2[k]);
                ull e = addx2(w, uj2);
                float el, eh; unpack2(e, el, eh);
                // skip contributions < 2^-40 (~1e-12): bias far below tolerance
                if (el > -40.f) atomicAdd(rowdst + 32 * k,       ex2(el));
                if (eh > -40.f) atomicAdd(rowdst + 32 * k + 256, ex2(eh));
            }
        }
    }
}

// ---------------------------------------------------------------------------
// Stage 3: out[tok, k] = sum_h src[tok,h] * ( sumP[b,h,k]*2000 + delta[h,k] )
// 8 tokens per CTA (groups never straddle a batch: 128 % 8 == 0).
// ---------------------------------------------------------------------------
#define OTPG 8
__global__ void __launch_bounds__(HDIM) out_kernel(
    const float* __restrict__ delta, float* __restrict__ out)
{
    const int tok0 = blockIdx.x * OTPG;
    const int bat  = tok0 >> 7;
    __shared__ float sr[OTPG][HDIM];   // 16 KB
    for (int idx = threadIdx.x; idx < OTPG * HDIM; idx += HDIM)
        sr[idx >> 9][idx & 511] = g_src[tok0 * HDIM + idx];
    __syncthreads();

    const int k = threadIdx.x;
    const float* P = g_sumP + (size_t)bat * HDIM * HDIM;
    float acc[OTPG];
#pragma unroll
    for (int t = 0; t < OTPG; t++) acc[t] = 0.f;
#pragma unroll 4
    for (int h = 0; h < HDIM; h++) {
        float p = fmaf(P[h * HDIM + k], 2000.0f, delta[h * HDIM + k]);
#pragma unroll
        for (int t = 0; t < OTPG; t++)
            acc[t] = fmaf(sr[t][h], p, acc[t]);
    }
#pragma unroll
    for (int t = 0; t < OTPG; t++)
        out[(tok0 + t) * HDIM + k] = acc[t];
}

// ---------------------------------------------------------------------------
extern "C" void kernel_launch(void* const* d_in, const int* in_sizes, int n_in,
                              void* d_out, int out_size)
{
    const float* X     = (const float*)d_in[0];  // (2,128,768)
    const float* Y     = (const float*)d_in[1];  // (2,128,512)
    const float* W     = (const float*)d_in[2];  // (512,768)
    const float* b     = (const float*)d_in[3];  // (512)
    const float* delta = (const float*)d_in[4];  // (512,512)
    float* out = (float*)d_out;                  // (2,128,512)

    zero_kernel<<<(BATCH * HDIM * HDIM / 4) / 256, 256>>>();
    src_kernel<<<NTOK / TPG, HDIM>>>(X, W, b);
    sinkhorn_kernel<<<NTOK, 512>>>(Y);
    out_kernel<<<NTOK / OTPG, HDIM>>>(delta, out);
}

// round 4
// speedup vs baseline: 1.1965x; 1.0663x over previous
#include <cuda_runtime.h>

// Problem constants
#define HDIM   512
#define BATCH  2
#define SEQ    128
#define DSRC   768
#define NTOK   (BATCH * SEQ)   // 256
#define NITER  30

// -(SCALE/REG) * log2(e) = -5000 * 1.4426950408889634
#define NEGC  (-7213.4752044448170f)
// -log2(H)
#define LOGMARG2 (-9.0f)

typedef unsigned long long ull;

// Scratch (static device globals; no runtime allocation allowed)
__device__ float g_src[NTOK * HDIM];            // 512 KB
__device__ float g_sumP[BATCH * HDIM * HDIM];   // 2 MB

// ---------------------------------------------------------------------------
// PTX helpers: fp32 MUFU + Blackwell packed f32x2
// ---------------------------------------------------------------------------
__device__ __forceinline__ float ex2(float x) {
    float y; asm("ex2.approx.f32 %0, %1;" : "=f"(y) : "f"(x)); return y;
}
__device__ __forceinline__ float lg2(float x) {
    float y; asm("lg2.approx.f32 %0, %1;" : "=f"(y) : "f"(x)); return y;
}
__device__ __forceinline__ ull pack2(float lo, float hi) {
    ull r; asm("mov.b64 %0, {%1, %2};" : "=l"(r) : "f"(lo), "f"(hi)); return r;
}
__device__ __forceinline__ void unpack2(ull v, float& lo, float& hi) {
    asm("mov.b64 {%0, %1}, %2;" : "=f"(lo), "=f"(hi) : "l"(v));
}
__device__ __forceinline__ ull subx2(ull a, ull b) {
    ull r; asm("sub.rn.f32x2 %0, %1, %2;" : "=l"(r) : "l"(a), "l"(b)); return r;
}
__device__ __forceinline__ ull addx2(ull a, ull b) {
    ull r; asm("add.rn.f32x2 %0, %1, %2;" : "=l"(r) : "l"(a), "l"(b)); return r;
}
__device__ __forceinline__ ull mulx2(ull a, ull b) {
    ull r; asm("mul.rn.f32x2 %0, %1, %2;" : "=l"(r) : "l"(a), "l"(b)); return r;
}
__device__ __forceinline__ ull fmax2p(ull a, ull b, ull c) {
    ull r; asm("fma.rn.f32x2 %0, %1, %2, %3;" : "=l"(r) : "l"(a), "l"(b), "l"(c)); return r;
}

// ---------------------------------------------------------------------------
// Stage 0: zero the plan accumulator (graph replays -> must run every launch)
// ---------------------------------------------------------------------------
__global__ void zero_kernel() {
    int i = blockIdx.x * blockDim.x + threadIdx.x;
    float4 z = make_float4(0.f, 0.f, 0.f, 0.f);
    reinterpret_cast<float4*>(g_sumP)[i] = z;   // grid sized exactly
}

// ---------------------------------------------------------------------------
// Stage 1: src[tok, h] = X[tok] . W[h] + b[h]   (4 tokens per CTA)
// ---------------------------------------------------------------------------
#define TPG 4
__global__ void __launch_bounds__(HDIM) src_kernel(
    const float* __restrict__ X, const float* __restrict__ W,
    const float* __restrict__ b)
{
    const int tok0 = blockIdx.x * TPG;
    __shared__ __align__(16) float xs[TPG][DSRC];   // 12 KB
    for (int idx = threadIdx.x; idx < TPG * DSRC; idx += HDIM)
        xs[idx / DSRC][idx % DSRC] = X[tok0 * DSRC + idx];
    __syncthreads();

    const int h = threadIdx.x;
    const float4* wr = reinterpret_cast<const float4*>(W + (size_t)h * DSRC);
    float acc0 = 0.f, acc1 = 0.f, acc2 = 0.f, acc3 = 0.f;
#pragma unroll 4
    for (int q = 0; q < DSRC / 4; q++) {
        float4 w4 = wr[q];
        float4 x0 = reinterpret_cast<const float4*>(xs[0])[q];
        float4 x1 = reinterpret_cast<const float4*>(xs[1])[q];
        float4 x2 = reinterpret_cast<const float4*>(xs[2])[q];
        float4 x3 = reinterpret_cast<const float4*>(xs[3])[q];
        acc0 = fmaf(w4.x, x0.x, acc0); acc0 = fmaf(w4.y, x0.y, acc0);
        acc0 = fmaf(w4.z, x0.z, acc0); acc0 = fmaf(w4.w, x0.w, acc0);
        acc1 = fmaf(w4.x, x1.x, acc1); acc1 = fmaf(w4.y, x1.y, acc1);
        acc1 = fmaf(w4.z, x1.z, acc1); acc1 = fmaf(w4.w, x1.w, acc1);
        acc2 = fmaf(w4.x, x2.x, acc2); acc2 = fmaf(w4.y, x2.y, acc2);
        acc2 = fmaf(w4.z, x2.z, acc2); acc2 = fmaf(w4.w, x2.w, acc2);
        acc3 = fmaf(w4.x, x3.x, acc3); acc3 = fmaf(w4.y, x3.y, acc3);
        acc3 = fmaf(w4.z, x3.z, acc3); acc3 = fmaf(w4.w, x3.w, acc3);
    }
    float bh = b[h];
    g_src[(tok0 + 0) * HDIM + h] = acc0 + bh;
    g_src[(tok0 + 1) * HDIM + h] = acc1 + bh;
    g_src[(tok0 + 2) * HDIM + h] = acc2 + bh;
    g_src[(tok0 + 3) * HDIM + h] = acc3 + bh;
}

// ---------------------------------------------------------------------------
// Warp-collective base-2 LSE of one row:
//   lse = log2( sum_i 2^( NEGC*(col_i - rowval)^2 + dual_i ) )
// colv/dualv: 8 packed f32x2 regs covering columns (lane+32k, lane+32k+256).
// All lanes return the same lse.
// ---------------------------------------------------------------------------
__device__ __forceinline__ float warp_lse(const ull* colv, const ull* dualv,
                                          float rowval, ull negc2)
{
    const ull r2 = pack2(rowval, rowval);
    ull w[8];
    float m0 = -3.402823466e+38f, m1 = -3.402823466e+38f;
#pragma unroll
    for (int k = 0; k < 8; k++) {
        ull d = subx2(colv[k], r2);           // s - t
        ull q = mulx2(d, d);                  // (s-t)^2
        w[k] = fmax2p(q, negc2, dualv[k]);    // NEGC*(s-t)^2 + dual
        float wl, wh; unpack2(w[k], wl, wh);
        m0 = fmaxf(m0, wl); m1 = fmaxf(m1, wh);
    }
    float m = fmaxf(m0, m1);
#pragma unroll
    for (int o = 16; o; o >>= 1)
        m = fmaxf(m, __shfl_xor_sync(0xffffffffu, m, o));
    const ull m2 = pack2(m, m);
    float a0 = 0.f, a1 = 0.f;
#pragma unroll
    for (int k = 0; k < 8; k++) {
        ull e = subx2(w[k], m2);
        float el, eh; unpack2(e, el, eh);
        a0 += ex2(el);
        a1 += ex2(eh);
    }
    float a = a0 + a1;
#pragma unroll
    for (int o = 16; o; o >>= 1)
        a += __shfl_xor_sync(0xffffffffu, a, o);
    return m + lg2(a);
}

// ---------------------------------------------------------------------------
// Stage 2: per-token log-domain (base-2) Sinkhorn + plan accumulation.
// One CTA per token, 512 threads = 16 warps. Warp w handles row-pairs
// p = w + 16*rr (rr = 0..15), i.e. rows p (low half) and p+256 (high half).
// SMEM float2 arrays pair indices (m, m+256), so pair index == array index.
// ---------------------------------------------------------------------------
__global__ void __launch_bounds__(512, 2) sinkhorn_kernel(
    const float* __restrict__ Y)
{
    const int tok  = blockIdx.x;
    const int bat  = tok >> 7;
    const int tid  = threadIdx.x;
    const int lane = tid & 31;
    const int warp = tid >> 5;

    __shared__ __align__(8) float2 sp[256];   // (s[m], s[m+256])
    __shared__ __align__(8) float2 tp[256];   // (t[m], t[m+256])
    __shared__ __align__(8) float2 up[256];   // (u[m], u[m+256])
    __shared__ __align__(8) float2 vp[256];   // (v[m], v[m+256])

    if (tid < 256) {
        sp[tid] = make_float2(g_src[tok * HDIM + tid], g_src[tok * HDIM + tid + 256]);
        tp[tid] = make_float2(Y[tok * HDIM + tid],     Y[tok * HDIM + tid + 256]);
        up[tid] = make_float2(0.f, 0.f);
        vp[tid] = make_float2(0.f, 0.f);
    }
    __syncthreads();

    const ull negc2 = pack2(NEGC, NEGC);
    const ull* sp_p = reinterpret_cast<const ull*>(sp);
    const ull* tp_p = reinterpret_cast<const ull*>(tp);
    const ull* up_p = reinterpret_cast<const ull*>(up);
    const ull* vp_p = reinterpret_cast<const ull*>(vp);

    for (int it = 0; it < NITER; it++) {
        // ---- u-pass: u[j] = -9 - lse_i( NEGC*(s_i - t_j)^2 + v_i ) ----
        {
            ull c2[8], d2[8];
#pragma unroll
            for (int k = 0; k < 8; k++) {
                c2[k] = sp_p[lane + 32 * k];
                d2[k] = vp_p[lane + 32 * k];
            }
#pragma unroll 1
            for (int rr = 0; rr < 16; rr++) {
                const int p = warp + 16 * rr;
                float2 tj = tp[p];
                float lseA = warp_lse(c2, d2, tj.x, negc2);
                float lseB = warp_lse(c2, d2, tj.y, negc2);
                if (lane == 0)
                    up[p] = make_float2(LOGMARG2 - lseA, LOGMARG2 - lseB);
            }
        }
        __syncthreads();

        // ---- v-pass: v[i] = -9 - lse_j( NEGC*(s_i - t_j)^2 + u_j ) ----
        {
            ull c2[8], d2[8];
#pragma unroll
            for (int k = 0; k < 8; k++) {
                c2[k] = tp_p[lane + 32 * k];
                d2[k] = up_p[lane + 32 * k];
            }
#pragma unroll 1
            for (int rr = 0; rr < 16; rr++) {
                const int p = warp + 16 * rr;
                float2 si = sp[p];
                float lseA = warp_lse(c2, d2, si.x, negc2);
                float lseB = warp_lse(c2, d2, si.y, negc2);
                if (lane == 0)
                    vp[p] = make_float2(LOGMARG2 - lseA, LOGMARG2 - lseB);
            }
        }
        __syncthreads();
    }

    // ---- Plan: P[j,i] = 2^( NEGC*(s_i - t_j)^2 + u_j + v_i ), accumulate ----
    {
        float* dst = g_sumP + (size_t)bat * HDIM * HDIM;
        ull c2[8], d2[8];
#pragma unroll
        for (int k = 0; k < 8; k++) {
            c2[k] = sp_p[lane + 32 * k];
            d2[k] = vp_p[lane + 32 * k];
        }
#pragma unroll 1
        for (int rr = 0; rr < 16; rr++) {
            const int p = warp + 16 * rr;
            float2 tj = tp[p];
            float2 uj = up[p];
#pragma unroll
            for (int half = 0; half < 2; half++) {
                const int j = p + half * 256;
                const float tjv = half ? tj.y : tj.x;
                const float ujv = half ? uj.y : uj.x;
                const ull t2 = pack2(tjv, tjv);
                const ull u2 = pack2(ujv, ujv);
                float* rowdst = dst + j * HDIM + lane;
#pragma unroll
                for (int k = 0; k < 8; k++) {
                    ull d = subx2(c2[k], t2);
                    ull q = mulx2(d, d);
                    ull w = fmax2p(q, negc2, d2[k]);
                    ull e = addx2(w, u2);
                    float el, eh; unpack2(e, el, eh);
                    // skip contributions < 2^-40 (~1e-12): bias far below tol
                    if (el > -40.f) atomicAdd(rowdst + 32 * k,       ex2(el));
                    if (eh > -40.f) atomicAdd(rowdst + 32 * k + 256, ex2(eh));
                }
            }
        }
    }
}

// ---------------------------------------------------------------------------
// Stage 3: out[tok, k] = sum_h src[tok,h] * ( sumP[b,h,k]*2000 + delta[h,k] )
// Grid (32 token-groups of 8, 4 column-slices of 128), block 128.
// ---------------------------------------------------------------------------
#define OTPG 8
__global__ void __launch_bounds__(128) out_kernel(
    const float* __restrict__ delta, float* __restrict__ out)
{
    const int tok0 = blockIdx.x * OTPG;
    const int bat  = tok0 >> 7;
    const int k    = blockIdx.y * 128 + threadIdx.x;

    __shared__ float sr[OTPG][HDIM];   // 16 KB
    for (int idx = threadIdx.x; idx < OTPG * HDIM; idx += 128)
        sr[idx >> 9][idx & 511] = g_src[tok0 * HDIM + idx];
    __syncthreads();

    const float* P = g_sumP + (size_t)bat * HDIM * HDIM;
    float acc[OTPG];
#pragma unroll
    for (int t = 0; t < OTPG; t++) acc[t] = 0.f;
#pragma unroll 4
    for (int h = 0; h < HDIM; h++) {
        float pv = fmaf(P[h * HDIM + k], 2000.0f, delta[h * HDIM + k]);
#pragma unroll
        for (int t = 0; t < OTPG; t++)
            acc[t] = fmaf(sr[t][h], pv, acc[t]);
    }
#pragma unroll
    for (int t = 0; t < OTPG; t++)
        out[(tok0 + t) * HDIM + k] = acc[t];
}

// ---------------------------------------------------------------------------
extern "C" void kernel_launch(void* const* d_in, const int* in_sizes, int n_in,
                              void* d_out, int out_size)
{
    const float* X     = (const float*)d_in[0];  // (2,128,768)
    const float* Y     = (const float*)d_in[1];  // (2,128,512)
    const float* W     = (const float*)d_in[2];  // (512,768)
    const float* b     = (const float*)d_in[3];  // (512)
    const float* delta = (const float*)d_in[4];  // (512,512)
    float* out = (float*)d_out;                  // (2,128,512)

    zero_kernel<<<(BATCH * HDIM * HDIM / 4) / 256, 256>>>();
    src_kernel<<<NTOK / TPG, HDIM>>>(X, W, b);
    sinkhorn_kernel<<<NTOK, 512>>>(Y);
    dim3 ogrid(NTOK / OTPG, HDIM / 128);
    out_kernel<<<ogrid, 128>>>(delta, out);
}

// round 6
// speedup vs baseline: 1.4194x; 1.1863x over previous
#include <cuda_runtime.h>

// Problem constants
#define HDIM   512
#define BATCH  2
#define SEQ    128
#define DSRC   768
#define NTOK   (BATCH * SEQ)   // 256
#define NITER  30
#define NSAFE  3               // iterations using exact max-LSE

// -(SCALE/REG) * log2(e) = -5000 * 1.4426950408889634
#define NEGC  (-7213.4752044448170f)
// -log2(H)
#define LOGMARG2 (-9.0f)

typedef unsigned long long ull;

// Scratch (static device globals; no runtime allocation allowed)
__device__ float g_src[NTOK * HDIM];            // 512 KB
__device__ float g_sumP[BATCH * HDIM * HDIM];   // 2 MB

// ---------------------------------------------------------------------------
// PTX helpers: fp32 MUFU + Blackwell packed f32x2
// ---------------------------------------------------------------------------
__device__ __forceinline__ float ex2(float x) {
    float y; asm("ex2.approx.f32 %0, %1;" : "=f"(y) : "f"(x)); return y;
}
__device__ __forceinline__ float lg2(float x) {
    float y; asm("lg2.approx.f32 %0, %1;" : "=f"(y) : "f"(x)); return y;
}
__device__ __forceinline__ ull pack2(float lo, float hi) {
    ull r; asm("mov.b64 %0, {%1, %2};" : "=l"(r) : "f"(lo), "f"(hi)); return r;
}
__device__ __forceinline__ void unpack2(ull v, float& lo, float& hi) {
    asm("mov.b64 {%0, %1}, %2;" : "=f"(lo), "=f"(hi) : "l"(v));
}
__device__ __forceinline__ ull subx2(ull a, ull b) {
    ull r; asm("sub.rn.f32x2 %0, %1, %2;" : "=l"(r) : "l"(a), "l"(b)); return r;
}
__device__ __forceinline__ ull addx2(ull a, ull b) {
    ull r; asm("add.rn.f32x2 %0, %1, %2;" : "=l"(r) : "l"(a), "l"(b)); return r;
}
__device__ __forceinline__ ull mulx2(ull a, ull b) {
    ull r; asm("mul.rn.f32x2 %0, %1, %2;" : "=l"(r) : "l"(a), "l"(b)); return r;
}
__device__ __forceinline__ ull fmax2p(ull a, ull b, ull c) {
    ull r; asm("fma.rn.f32x2 %0, %1, %2, %3;" : "=l"(r) : "l"(a), "l"(b), "l"(c)); return r;
}

// ---------------------------------------------------------------------------
// Stage 0: zero the plan accumulator (graph replays -> must run every launch)
// ---------------------------------------------------------------------------
__global__ void zero_kernel() {
    int i = blockIdx.x * blockDim.x + threadIdx.x;
    float4 z = make_float4(0.f, 0.f, 0.f, 0.f);
    reinterpret_cast<float4*>(g_sumP)[i] = z;   // grid sized exactly
}

// ---------------------------------------------------------------------------
// Stage 1: src[tok, h] = X[tok] . W[h] + b[h]   (4 tokens per CTA)
// ---------------------------------------------------------------------------
#define TPG 4
__global__ void __launch_bounds__(HDIM) src_kernel(
    const float* __restrict__ X, const float* __restrict__ W,
    const float* __restrict__ b)
{
    const int tok0 = blockIdx.x * TPG;
    __shared__ __align__(16) float xs[TPG][DSRC];   // 12 KB
    for (int idx = threadIdx.x; idx < TPG * DSRC; idx += HDIM)
        xs[idx / DSRC][idx % DSRC] = X[tok0 * DSRC + idx];
    __syncthreads();

    const int h = threadIdx.x;
    const float4* wr = reinterpret_cast<const float4*>(W + (size_t)h * DSRC);
    float acc0 = 0.f, acc1 = 0.f, acc2 = 0.f, acc3 = 0.f;
#pragma unroll 4
    for (int q = 0; q < DSRC / 4; q++) {
        float4 w4 = wr[q];
        float4 x0 = reinterpret_cast<const float4*>(xs[0])[q];
        float4 x1 = reinterpret_cast<const float4*>(xs[1])[q];
        float4 x2 = reinterpret_cast<const float4*>(xs[2])[q];
        float4 x3 = reinterpret_cast<const float4*>(xs[3])[q];
        acc0 = fmaf(w4.x, x0.x, acc0); acc0 = fmaf(w4.y, x0.y, acc0);
        acc0 = fmaf(w4.z, x0.z, acc0); acc0 = fmaf(w4.w, x0.w, acc0);
        acc1 = fmaf(w4.x, x1.x, acc1); acc1 = fmaf(w4.y, x1.y, acc1);
        acc1 = fmaf(w4.z, x1.z, acc1); acc1 = fmaf(w4.w, x1.w, acc1);
        acc2 = fmaf(w4.x, x2.x, acc2); acc2 = fmaf(w4.y, x2.y, acc2);
        acc2 = fmaf(w4.z, x2.z, acc2); acc2 = fmaf(w4.w, x2.w, acc2);
        acc3 = fmaf(w4.x, x3.x, acc3); acc3 = fmaf(w4.y, x3.y, acc3);
        acc3 = fmaf(w4.z, x3.z, acc3); acc3 = fmaf(w4.w, x3.w, acc3);
    }
    float bh = b[h];
    g_src[(tok0 + 0) * HDIM + h] = acc0 + bh;
    g_src[(tok0 + 1) * HDIM + h] = acc1 + bh;
    g_src[(tok0 + 2) * HDIM + h] = acc2 + bh;
    g_src[(tok0 + 3) * HDIM + h] = acc3 + bh;
}

// ---------------------------------------------------------------------------
// Per-thread (in-lane) LSE over 512 columns stored as 256 packed pairs.
// col[c] packs (x_c, x_{c+256}); dual[c] packs the matching dual values.
// exponent(c) = NEGC*(col_c - rowval)^2 + dual_c
//
// lse_safe:  exact two-sweep (max then sum) -> returns lse (base 2)
// lse_delta: single sweep with known-good shift folded into `shift`
//            returns lg2( sum_c 2^( exponent(c) + shift ) )
// No warp reductions anywhere: max/sum are per-thread scalars.
// ---------------------------------------------------------------------------
__device__ __forceinline__ float lse_safe(const ull* __restrict__ col,
                                          const ull* __restrict__ dual,
                                          float rowval, ull negc2)
{
    const ull r2 = pack2(rowval, rowval);
    float m0 = -3.402823466e+38f, m1 = -3.402823466e+38f;
#pragma unroll 4
    for (int c = 0; c < 256; c++) {
        ull d = subx2(col[c], r2);
        ull q = mulx2(d, d);
        ull e = fmax2p(q, negc2, dual[c]);
        float el, eh; unpack2(e, el, eh);
        m0 = fmaxf(m0, el); m1 = fmaxf(m1, eh);
    }
    const float m = fmaxf(m0, m1);
    const ull m2 = pack2(m, m);
    float a0 = 1e-30f, a1 = 1e-30f;
#pragma unroll 4
    for (int c = 0; c < 256; c++) {
        ull d = subx2(col[c], r2);
        ull q = mulx2(d, d);
        ull e = fmax2p(q, negc2, dual[c]);
        ull e2 = subx2(e, m2);
        float el, eh; unpack2(e2, el, eh);
        a0 += ex2(el); a1 += ex2(eh);
    }
    return m + lg2(a0 + a1);
}

__device__ __forceinline__ float lse_delta(const ull* __restrict__ col,
                                           const ull* __restrict__ dual,
                                           float rowval, float shift, ull negc2)
{
    const ull r2 = pack2(rowval, rowval);
    const ull s2 = pack2(shift, shift);
    float a0 = 1e-30f, a1 = 1e-30f;
#pragma unroll 4
    for (int c = 0; c < 256; c++) {
        ull d  = subx2(col[c], r2);
        ull q  = mulx2(d, d);
        ull vm = addx2(dual[c], s2);
        ull e  = fmax2p(q, negc2, vm);
        float el, eh; unpack2(e, el, eh);
        a0 += ex2(el); a1 += ex2(eh);
    }
    return lg2(a0 + a1);
}

// ---------------------------------------------------------------------------
// Stage 2: per-token base-2 log-domain Sinkhorn, transposed parallelization:
// thread tid owns row j=tid in u-passes and column i=tid in v-passes; the
// 512-wide inner reduction is an in-lane loop over SMEM (broadcast reads).
// Iterations 0..NSAFE-1 use exact max-LSE; the rest use the previous dual
// as LSE shift: after each half-update the matrix logK+u+v+9 has all terms
// <= 0 and row/col sums ~ 1, so u_new = u_old - lg2( sum 2^(logK+v+u_old+9) )
// is exact (identical math to reference, different rounding only).
// ---------------------------------------------------------------------------
__global__ void __launch_bounds__(512, 2) sinkhorn_kernel(
    const float* __restrict__ Y)
{
    const int tok  = blockIdx.x;
    const int bat  = tok >> 7;
    const int tid  = threadIdx.x;
    const int base = tid & 255;
    const int half = tid >> 8;

    __shared__ __align__(8) float2 sp[256];   // (s[m], s[m+256])
    __shared__ __align__(8) float2 tp[256];   // (t[m], t[m+256])
    __shared__ __align__(8) float2 up[256];   // (u[m], u[m+256])
    __shared__ __align__(8) float2 vp[256];   // (v[m], v[m+256])

    if (tid < 256) {
        sp[tid] = make_float2(g_src[tok * HDIM + tid], g_src[tok * HDIM + tid + 256]);
        tp[tid] = make_float2(Y[tok * HDIM + tid],     Y[tok * HDIM + tid + 256]);
        up[tid] = make_float2(0.f, 0.f);
        vp[tid] = make_float2(0.f, 0.f);
    }
    __syncthreads();

    const ull negc2 = pack2(NEGC, NEGC);
    const ull* sp_p = reinterpret_cast<const ull*>(sp);
    const ull* tp_p = reinterpret_cast<const ull*>(tp);
    const ull* up_p = reinterpret_cast<const ull*>(up);
    const ull* vp_p = reinterpret_cast<const ull*>(vp);
    float* up_s = reinterpret_cast<float*>(up);
    float* vp_s = reinterpret_cast<float*>(vp);

    const float t_own = half ? tp[base].y : tp[base].x;  // row value (u-pass)
    const float s_own = half ? sp[base].y : sp[base].x;  // col value (v-pass)
    const int own_off = base * 2 + half;                 // scalar index in pair array

    float u_own = 0.f, v_own = 0.f;

    for (int it = 0; it < NITER; it++) {
        // ---- u-update: u[j] = -9 - lse_i( NEGC*(s_i-t_j)^2 + v_i ) ----
        if (it < NSAFE) {
            u_own = LOGMARG2 - lse_safe(sp_p, vp_p, t_own, negc2);
        } else {
            u_own -= lse_delta(sp_p, vp_p, t_own, u_own + 9.0f, negc2);
        }
        up_s[own_off] = u_own;
        __syncthreads();

        // ---- v-update: v[i] = -9 - lse_j( NEGC*(s_i-t_j)^2 + u_j ) ----
        if (it < NSAFE) {
            v_own = LOGMARG2 - lse_safe(tp_p, up_p, s_own, negc2);
        } else {
            v_own -= lse_delta(tp_p, up_p, s_own, v_own + 9.0f, negc2);
        }
        vp_s[own_off] = v_own;
        __syncthreads();
    }

    // ---- Plan: P[j,i] = 2^( NEGC*(s_i-t_j)^2 + u_j + v_i ), accumulate ----
    {
        float* rowdst = g_sumP + (size_t)bat * HDIM * HDIM + tid * HDIM;
        const ull r2 = pack2(t_own, t_own);
        const ull u2 = pack2(u_own, u_own);
#pragma unroll 4
        for (int c = 0; c < 256; c++) {
            ull d  = subx2(sp_p[c], r2);
            ull q  = mulx2(d, d);
            ull vm = addx2(vp_p[c], u2);
            ull e  = fmax2p(q, negc2, vm);
            float el, eh; unpack2(e, el, eh);
            // skip contributions < 2^-40 (~1e-12): bias far below tolerance
            if (el > -40.f) atomicAdd(rowdst + c,       ex2(el));
            if (eh > -40.f) atomicAdd(rowdst + c + 256, ex2(eh));
        }
    }
}

// ---------------------------------------------------------------------------
// Stage 3: out[tok, k] = sum_h src[tok,h] * ( sumP[b,h,k]*2000 + delta[h,k] )
// 4 tokens per CTA, 256 threads, one float2 column per thread. Grid 64 CTAs;
// L2 traffic = 64 * 2 MB = 128 MB.
// ---------------------------------------------------------------------------
#define OTPG 4
__global__ void __launch_bounds__(256) out_kernel(
    const float* __restrict__ delta, float* __restrict__ out)
{
    const int tok0 = blockIdx.x * OTPG;
    const int bat  = tok0 >> 7;
    const int k2   = threadIdx.x;            // float2 column index (0..255)

    __shared__ float sr[OTPG][HDIM];         // 8 KB
    for (int idx = threadIdx.x; idx < OTPG * HDIM; idx += 256)
        sr[idx >> 9][idx & 511] = g_src[tok0 * HDIM + idx];
    __syncthreads();

    const float2* P2 = reinterpret_cast<const float2*>(
        g_sumP + (size_t)bat * HDIM * HDIM);
    const float2* D2 = reinterpret_cast<const float2*>(delta);

    float a0[OTPG], a1[OTPG];
#pragma unroll
    for (int t = 0; t < OTPG; t++) { a0[t] = 0.f; a1[t] = 0.f; }

#pragma unroll 8
    for (int h = 0; h < HDIM; h++) {
        float2 p = __ldg(&P2[h * 256 + k2]);
        float2 d = __ldg(&D2[h * 256 + k2]);
        float pv0 = fmaf(p.x, 2000.0f, d.x);
        float pv1 = fmaf(p.y, 2000.0f, d.y);
#pragma unroll
        for (int t = 0; t < OTPG; t++) {
            float s = sr[t][h];
            a0[t] = fmaf(s, pv0, a0[t]);
            a1[t] = fmaf(s, pv1, a1[t]);
        }
    }
    float2* O2 = reinterpret_cast<float2*>(out);
#pragma unroll
    for (int t = 0; t < OTPG; t++)
        O2[(tok0 + t) * 256 + k2] = make_float2(a0[t], a1[t]);
}

// ---------------------------------------------------------------------------
extern "C" void kernel_launch(void* const* d_in, const int* in_sizes, int n_in,
                              void* d_out, int out_size)
{
    const float* X     = (const float*)d_in[0];  // (2,128,768)
    const float* Y     = (const float*)d_in[1];  // (2,128,512)
    const float* W     = (const float*)d_in[2];  // (512,768)
    const float* b     = (const float*)d_in[3];  // (512)
    const float* delta = (const float*)d_in[4];  // (512,512)
    float* out = (float*)d_out;                  // (2,128,512)

    zero_kernel<<<(BATCH * HDIM * HDIM / 4) / 256, 256>>>();
    src_kernel<<<NTOK / TPG, HDIM>>>(X, W, b);
    sinkhorn_kernel<<<NTOK, 512>>>(Y);
    out_kernel<<<NTOK / OTPG, 256>>>(delta, out);
}

// round 7
// speedup vs baseline: 1.5339x; 1.0807x over previous
#include <cuda_runtime.h>

// Problem constants
#define HDIM   512
#define BATCH  2
#define SEQ    128
#define DSRC   768
#define NTOK   (BATCH * SEQ)   // 256
#define NITER  30
#define NSAFE  3               // iterations using exact max-LSE

// -(SCALE/REG) * log2(e) = -5000 * 1.4426950408889634
#define NEGC  (-7213.4752044448170f)
// -log2(H)
#define LOGMARG2 (-9.0f)

typedef unsigned long long ull;

// Scratch (static device globals; no runtime allocation allowed)
__device__ float g_src[NTOK * HDIM];            // 512 KB
__device__ float g_sumP[BATCH * HDIM * HDIM];   // 2 MB

// ---------------------------------------------------------------------------
// PTX helpers: fp32 MUFU + Blackwell packed f32x2
// ---------------------------------------------------------------------------
__device__ __forceinline__ float ex2(float x) {
    float y; asm("ex2.approx.f32 %0, %1;" : "=f"(y) : "f"(x)); return y;
}
__device__ __forceinline__ float lg2(float x) {
    float y; asm("lg2.approx.f32 %0, %1;" : "=f"(y) : "f"(x)); return y;
}
__device__ __forceinline__ ull pack2(float lo, float hi) {
    ull r; asm("mov.b64 %0, {%1, %2};" : "=l"(r) : "f"(lo), "f"(hi)); return r;
}
__device__ __forceinline__ void unpack2(ull v, float& lo, float& hi) {
    asm("mov.b64 {%0, %1}, %2;" : "=f"(lo), "=f"(hi) : "l"(v));
}
__device__ __forceinline__ ull subx2(ull a, ull b) {
    ull r; asm("sub.rn.f32x2 %0, %1, %2;" : "=l"(r) : "l"(a), "l"(b)); return r;
}
__device__ __forceinline__ ull addx2(ull a, ull b) {
    ull r; asm("add.rn.f32x2 %0, %1, %2;" : "=l"(r) : "l"(a), "l"(b)); return r;
}
__device__ __forceinline__ ull mulx2(ull a, ull b) {
    ull r; asm("mul.rn.f32x2 %0, %1, %2;" : "=l"(r) : "l"(a), "l"(b)); return r;
}
__device__ __forceinline__ ull fmax2p(ull a, ull b, ull c) {
    ull r; asm("fma.rn.f32x2 %0, %1, %2, %3;" : "=l"(r) : "l"(a), "l"(b), "l"(c)); return r;
}

// ---------------------------------------------------------------------------
// Stage 0: zero plan accumulator AND d_out (harness poisons it; out_kernel
// now accumulates with atomics). Graph replays -> must run every launch.
// ---------------------------------------------------------------------------
#define NZ_P   (BATCH * HDIM * HDIM / 4)   // 131072 float4
#define NZ_OUT (NTOK * HDIM / 4)           // 32768 float4
__global__ void zero_kernel(float* __restrict__ out) {
    int i = blockIdx.x * blockDim.x + threadIdx.x;
    float4 z = make_float4(0.f, 0.f, 0.f, 0.f);
    if (i < NZ_P) reinterpret_cast<float4*>(g_sumP)[i] = z;
    else          reinterpret_cast<float4*>(out)[i - NZ_P] = z;
}

// ---------------------------------------------------------------------------
// Stage 1: src[tok, h] = X[tok] . W[h] + b[h]   (4 tokens per CTA)
// ---------------------------------------------------------------------------
#define TPG 4
__global__ void __launch_bounds__(HDIM) src_kernel(
    const float* __restrict__ X, const float* __restrict__ W,
    const float* __restrict__ b)
{
    const int tok0 = blockIdx.x * TPG;
    __shared__ __align__(16) float xs[TPG][DSRC];   // 12 KB
    for (int idx = threadIdx.x; idx < TPG * DSRC; idx += HDIM)
        xs[idx / DSRC][idx % DSRC] = X[tok0 * DSRC + idx];
    __syncthreads();

    const int h = threadIdx.x;
    const float4* wr = reinterpret_cast<const float4*>(W + (size_t)h * DSRC);
    float acc0 = 0.f, acc1 = 0.f, acc2 = 0.f, acc3 = 0.f;
#pragma unroll 4
    for (int q = 0; q < DSRC / 4; q++) {
        float4 w4 = wr[q];
        float4 x0 = reinterpret_cast<const float4*>(xs[0])[q];
        float4 x1 = reinterpret_cast<const float4*>(xs[1])[q];
        float4 x2 = reinterpret_cast<const float4*>(xs[2])[q];
        float4 x3 = reinterpret_cast<const float4*>(xs[3])[q];
        acc0 = fmaf(w4.x, x0.x, acc0); acc0 = fmaf(w4.y, x0.y, acc0);
        acc0 = fmaf(w4.z, x0.z, acc0); acc0 = fmaf(w4.w, x0.w, acc0);
        acc1 = fmaf(w4.x, x1.x, acc1); acc1 = fmaf(w4.y, x1.y, acc1);
        acc1 = fmaf(w4.z, x1.z, acc1); acc1 = fmaf(w4.w, x1.w, acc1);
        acc2 = fmaf(w4.x, x2.x, acc2); acc2 = fmaf(w4.y, x2.y, acc2);
        acc2 = fmaf(w4.z, x2.z, acc2); acc2 = fmaf(w4.w, x2.w, acc2);
        acc3 = fmaf(w4.x, x3.x, acc3); acc3 = fmaf(w4.y, x3.y, acc3);
        acc3 = fmaf(w4.z, x3.z, acc3); acc3 = fmaf(w4.w, x3.w, acc3);
    }
    float bh = b[h];
    g_src[(tok0 + 0) * HDIM + h] = acc0 + bh;
    g_src[(tok0 + 1) * HDIM + h] = acc1 + bh;
    g_src[(tok0 + 2) * HDIM + h] = acc2 + bh;
    g_src[(tok0 + 3) * HDIM + h] = acc3 + bh;
}

// ---------------------------------------------------------------------------
// In-lane LSE over 512 columns. arr[c] is a ulonglong2:
//   .x packs (val_c, val_{c+256}), .y packs (dual_c, dual_{c+256}).
// exponent(c) = NEGC*(val_c - rowval)^2 + dual_c (+ shift in lse_shift4).
// lse_safe4: exact two-sweep max-LSE.  lse_shift4: single sweep, shift known
// to keep every term <= 0 (post-normalization invariant).
// ---------------------------------------------------------------------------
__device__ __forceinline__ float lse_safe4(const ulonglong2* __restrict__ arr,
                                           float rowval, ull negc2)
{
    const ull r2 = pack2(rowval, rowval);
    float m0 = -3.402823466e+38f, m1 = -3.402823466e+38f;
#pragma unroll 8
    for (int c = 0; c < 256; c++) {
        ulonglong2 q = arr[c];
        ull d = subx2(q.x, r2);
        ull sq = mulx2(d, d);
        ull e = fmax2p(sq, negc2, q.y);
        float el, eh; unpack2(e, el, eh);
        m0 = fmaxf(m0, el); m1 = fmaxf(m1, eh);
    }
    const float m = fmaxf(m0, m1);
    const ull m2 = pack2(m, m);
    float a0 = 1e-30f, a1 = 1e-30f;
#pragma unroll 8
    for (int c = 0; c < 256; c++) {
        ulonglong2 q = arr[c];
        ull d = subx2(q.x, r2);
        ull sq = mulx2(d, d);
        ull e = fmax2p(sq, negc2, q.y);
        ull e2 = subx2(e, m2);
        float el, eh; unpack2(e2, el, eh);
        a0 += ex2(el); a1 += ex2(eh);
    }
    return m + lg2(a0 + a1);
}

__device__ __forceinline__ float lse_shift4(const ulonglong2* __restrict__ arr,
                                            float rowval, float shift, ull negc2)
{
    const ull r2 = pack2(rowval, rowval);
    const ull s2 = pack2(shift, shift);
    float a0 = 1e-30f, a1 = 1e-30f;
#pragma unroll 8
    for (int c = 0; c < 256; c++) {
        ulonglong2 q = arr[c];
        ull d  = subx2(q.x, r2);
        ull sq = mulx2(d, d);
        ull vm = addx2(q.y, s2);
        ull e  = fmax2p(sq, negc2, vm);
        float el, eh; unpack2(e, el, eh);
        a0 += ex2(el); a1 += ex2(eh);
    }
    return lg2(a0 + a1);
}

// ---------------------------------------------------------------------------
// Stage 2: per-token base-2 log-domain Sinkhorn, transposed parallelization.
// Thread tid owns row j=tid (u) and column i=tid (v). SMEM arrays fuse value
// and dual: SV[c] = (s_c, s_{c+256}, v_c, v_{c+256}); TU = (t, t', u, u').
// One broadcast LDS.128 per inner step. Iterations >= NSAFE use the previous
// dual as LSE shift (valid: after each half-normalization every term of
// logK+u+v+9 is <= 0 with max >= ~-9, so no overflow/underflow).
// ---------------------------------------------------------------------------
__global__ void __launch_bounds__(512, 2) sinkhorn_kernel(
    const float* __restrict__ Y)
{
    const int tok  = blockIdx.x;
    const int bat  = tok >> 7;
    const int tid  = threadIdx.x;
    const int base = tid & 255;
    const int half = tid >> 8;

    __shared__ __align__(16) ulonglong2 SV[256];   // (s,s',v,v')
    __shared__ __align__(16) ulonglong2 TU[256];   // (t,t',u,u')

    if (tid < 256) {
        float s0 = g_src[tok * HDIM + tid];
        float s1 = g_src[tok * HDIM + tid + 256];
        float t0 = Y[tok * HDIM + tid];
        float t1 = Y[tok * HDIM + tid + 256];
        SV[tid].x = pack2(s0, s1);  SV[tid].y = 0ull;
        TU[tid].x = pack2(t0, t1);  TU[tid].y = 0ull;
    }
    __syncthreads();

    const ull negc2 = pack2(NEGC, NEGC);
    float t_own, s_own;
    {
        float a, bx; unpack2(TU[base].x, a, bx); t_own = half ? bx : a;
        float c, d2; unpack2(SV[base].x, c, d2); s_own = half ? d2 : c;
    }
    // scalar slots of the dual halves: word index base*4 + 2 + half
    float* SV_s = reinterpret_cast<float*>(SV);
    float* TU_s = reinterpret_cast<float*>(TU);
    const int own_off = base * 4 + 2 + half;

    float u_own = 0.f, v_own = 0.f;

    for (int it = 0; it < NITER; it++) {
        // ---- u-update: u[j] = -9 - lse_i( NEGC*(s_i-t_j)^2 + v_i ) ----
        if (it < NSAFE) {
            u_own = LOGMARG2 - lse_safe4(SV, t_own, negc2);
        } else {
            u_own -= lse_shift4(SV, t_own, u_own + 9.0f, negc2);
        }
        TU_s[own_off] = u_own;
        __syncthreads();

        // ---- v-update: v[i] = -9 - lse_j( NEGC*(s_i-t_j)^2 + u_j ) ----
        if (it < NSAFE) {
            v_own = LOGMARG2 - lse_safe4(TU, s_own, negc2);
        } else {
            v_own -= lse_shift4(TU, s_own, v_own + 9.0f, negc2);
        }
        SV_s[own_off] = v_own;
        __syncthreads();
    }

    // ---- Plan: P[j,i] = 2^( NEGC*(s_i-t_j)^2 + u_j + v_i ), accumulate ----
    {
        float* rowdst = g_sumP + (size_t)bat * HDIM * HDIM + tid * HDIM;
        const ull r2 = pack2(t_own, t_own);
        const ull u2 = pack2(u_own, u_own);
#pragma unroll 4
        for (int c = 0; c < 256; c++) {
            ulonglong2 q = SV[c];
            ull d  = subx2(q.x, r2);
            ull sq = mulx2(d, d);
            ull vm = addx2(q.y, u2);
            ull e  = fmax2p(sq, negc2, vm);
            float el, eh; unpack2(e, el, eh);
            // skip contributions < 2^-40 (~1e-12): bias far below tolerance
            if (el > -40.f) atomicAdd(rowdst + c,       ex2(el));
            if (eh > -40.f) atomicAdd(rowdst + c + 256, ex2(eh));
        }
    }
}

// ---------------------------------------------------------------------------
// Stage 3: out[tok, k] += sum_{h in slice} src[tok,h]*(sumP[b,h,k]*2000
//                                                      + delta[h,k])
// Grid (16 token-groups of 16, 8 h-slices of 64). 128 CTAs, 256 threads.
// L2 traffic: 128 CTAs * 256 KB = 32 MB. Partials merged via atomicAdd
// (out zeroed in zero_kernel).
// ---------------------------------------------------------------------------
#define OT_TOK 16
#define OT_H   64
__global__ void __launch_bounds__(256) out_kernel(
    const float* __restrict__ delta, float* __restrict__ out)
{
    const int tok0 = blockIdx.x * OT_TOK;
    const int h0   = blockIdx.y * OT_H;
    const int bat  = tok0 >> 7;       // OT_TOK divides SEQ -> no straddle
    const int k2   = threadIdx.x;     // float2 column index (0..255)

    __shared__ float sr[OT_TOK][OT_H];   // 4 KB
    for (int idx = threadIdx.x; idx < OT_TOK * OT_H; idx += 256)
        sr[idx / OT_H][idx % OT_H] = g_src[(tok0 + idx / OT_H) * HDIM + h0 + idx % OT_H];
    __syncthreads();

    const float2* P2 = reinterpret_cast<const float2*>(
        g_sumP + (size_t)bat * HDIM * HDIM);
    const float2* D2 = reinterpret_cast<const float2*>(delta);

    float a0[OT_TOK], a1[OT_TOK];
#pragma unroll
    for (int t = 0; t < OT_TOK; t++) { a0[t] = 0.f; a1[t] = 0.f; }

#pragma unroll 4
    for (int h = 0; h < OT_H; h++) {
        float2 p = __ldg(&P2[(h0 + h) * 256 + k2]);
        float2 d = __ldg(&D2[(h0 + h) * 256 + k2]);
        float pv0 = fmaf(p.x, 2000.0f, d.x);
        float pv1 = fmaf(p.y, 2000.0f, d.y);
#pragma unroll
        for (int t = 0; t < OT_TOK; t++) {
            float s = sr[t][h];
            a0[t] = fmaf(s, pv0, a0[t]);
            a1[t] = fmaf(s, pv1, a1[t]);
        }
    }
#pragma unroll
    for (int t = 0; t < OT_TOK; t++) {
        atomicAdd(&out[(tok0 + t) * HDIM + 2 * k2],     a0[t]);
        atomicAdd(&out[(tok0 + t) * HDIM + 2 * k2 + 1], a1[t]);
    }
}

// ---------------------------------------------------------------------------
extern "C" void kernel_launch(void* const* d_in, const int* in_sizes, int n_in,
                              void* d_out, int out_size)
{
    const float* X     = (const float*)d_in[0];  // (2,128,768)
    const float* Y     = (const float*)d_in[1];  // (2,128,512)
    const float* W     = (const float*)d_in[2];  // (512,768)
    const float* b     = (const float*)d_in[3];  // (512)
    const float* delta = (const float*)d_in[4];  // (512,512)
    float* out = (float*)d_out;                  // (2,128,512)

    zero_kernel<<<(NZ_P + NZ_OUT) / 256, 256>>>(out);
    src_kernel<<<NTOK / TPG, HDIM>>>(X, W, b);
    sinkhorn_kernel<<<NTOK, 512>>>(Y);
    dim3 ogrid(NTOK / OT_TOK, HDIM / OT_H);
    out_kernel<<<ogrid, 256>>>(delta, out);
}

// round 8
// speedup vs baseline: 1.8630x; 1.2146x over previous
#include <cuda_runtime.h>

// Problem constants
#define HDIM   512
#define BATCH  2
#define SEQ    128
#define DSRC   768
#define NTOK   (BATCH * SEQ)   // 256
#define NITER  30

// -(SCALE/REG) * log2(e) = -5000 * 1.4426950408889634
#define NEGC  (-7213.4752044448170f)
#define CPOS  (7213.4752044448170f)
#define INVC  (1.3862943611198906e-4f)   // 1/CPOS
// -log2(H)
#define LOGMARG2 (-9.0f)
// window cutoff: terms below -TW match the dense-f32 anchor behavior exactly
#define TW 90.0f

typedef unsigned long long ull;

// Scratch (static device globals; no runtime allocation allowed)
__device__ float g_src[NTOK * HDIM];            // 512 KB
__device__ float g_sumP[BATCH * HDIM * HDIM];   // 2 MB

__device__ __forceinline__ float ex2(float x) {
    float y; asm("ex2.approx.f32 %0, %1;" : "=f"(y) : "f"(x)); return y;
}
__device__ __forceinline__ float lg2(float x) {
    float y; asm("lg2.approx.f32 %0, %1;" : "=f"(y) : "f"(x)); return y;
}

// ---------------------------------------------------------------------------
// Stage 0: zero plan accumulator AND d_out (harness poisons it; out_kernel
// accumulates with atomics). Graph replays -> must run every launch.
// ---------------------------------------------------------------------------
#define NZ_P   (BATCH * HDIM * HDIM / 4)   // 131072 float4
#define NZ_OUT (NTOK * HDIM / 4)           // 32768 float4
__global__ void zero_kernel(float* __restrict__ out) {
    int i = blockIdx.x * blockDim.x + threadIdx.x;
    float4 z = make_float4(0.f, 0.f, 0.f, 0.f);
    if (i < NZ_P) reinterpret_cast<float4*>(g_sumP)[i] = z;
    else          reinterpret_cast<float4*>(out)[i - NZ_P] = z;
}

// ---------------------------------------------------------------------------
// Stage 1: src[tok, h] = X[tok] . W[h] + b[h]   (4 tokens per CTA)
// ---------------------------------------------------------------------------
#define TPG 4
__global__ void __launch_bounds__(HDIM) src_kernel(
    const float* __restrict__ X, const float* __restrict__ W,
    const float* __restrict__ b)
{
    const int tok0 = blockIdx.x * TPG;
    __shared__ __align__(16) float xs[TPG][DSRC];   // 12 KB
    for (int idx = threadIdx.x; idx < TPG * DSRC; idx += HDIM)
        xs[idx / DSRC][idx % DSRC] = X[tok0 * DSRC + idx];
    __syncthreads();

    const int h = threadIdx.x;
    const float4* wr = reinterpret_cast<const float4*>(W + (size_t)h * DSRC);
    float acc0 = 0.f, acc1 = 0.f, acc2 = 0.f, acc3 = 0.f;
#pragma unroll 4
    for (int q = 0; q < DSRC / 4; q++) {
        float4 w4 = wr[q];
        float4 x0 = reinterpret_cast<const float4*>(xs[0])[q];
        float4 x1 = reinterpret_cast<const float4*>(xs[1])[q];
        float4 x2 = reinterpret_cast<const float4*>(xs[2])[q];
        float4 x3 = reinterpret_cast<const float4*>(xs[3])[q];
        acc0 = fmaf(w4.x, x0.x, acc0); acc0 = fmaf(w4.y, x0.y, acc0);
        acc0 = fmaf(w4.z, x0.z, acc0); acc0 = fmaf(w4.w, x0.w, acc0);
        acc1 = fmaf(w4.x, x1.x, acc1); acc1 = fmaf(w4.y, x1.y, acc1);
        acc1 = fmaf(w4.z, x1.z, acc1); acc1 = fmaf(w4.w, x1.w, acc1);
        acc2 = fmaf(w4.x, x2.x, acc2); acc2 = fmaf(w4.y, x2.y, acc2);
        acc2 = fmaf(w4.z, x2.z, acc2); acc2 = fmaf(w4.w, x2.w, acc2);
        acc3 = fmaf(w4.x, x3.x, acc3); acc3 = fmaf(w4.y, x3.y, acc3);
        acc3 = fmaf(w4.z, x3.z, acc3); acc3 = fmaf(w4.w, x3.w, acc3);
    }
    float bh = b[h];
    g_src[(tok0 + 0) * HDIM + h] = acc0 + bh;
    g_src[(tok0 + 1) * HDIM + h] = acc1 + bh;
    g_src[(tok0 + 2) * HDIM + h] = acc2 + bh;
    g_src[(tok0 + 3) * HDIM + h] = acc3 + bh;
}

// ---------------------------------------------------------------------------
// Binary search helpers over the sorted .x fields of a float2 array.
// ---------------------------------------------------------------------------
__device__ __forceinline__ int lbound(const float2* __restrict__ A, float x) {
    int lo = 0, hi = HDIM;
    while (lo < hi) { int m = (lo + hi) >> 1; if (A[m].x < x) lo = m + 1; else hi = m; }
    return lo;
}
__device__ __forceinline__ int ubound(const float2* __restrict__ A, float x) {
    int lo = 0, hi = HDIM;
    while (lo < hi) { int m = (lo + hi) >> 1; if (A[m].x <= x) lo = m + 1; else hi = m; }
    return lo;
}

// ---------------------------------------------------------------------------
// Stage 2: banded per-token base-2 log-domain Sinkhorn.
//
// s and t are bitonic-sorted (with original-index payloads). Thread tid owns
// sorted row tid (t side) and sorted column tid (s side). Each half-pass:
//   u_j <- u_j - lg2( sum_i 2^( -C*(s_i - t_j)^2 + v_i + u_j + 9 ) )
// computed only over the window |s_i - t_j| <= r_j with
//   r_j^2 = (TW + maxV + u_j + 9)/C,
// which keeps every term with tau >= -TW; dropped terms are below the f32
// anchor behavior of the dense kernel (identical result to < 2^-80).
// Init u_j = -9 + C*d_nn(j)^2 makes iteration 0 use the same code path
// (tau <= 0 exactly, window provably contains the max term).
// ---------------------------------------------------------------------------
__global__ void __launch_bounds__(512, 2) sinkhorn_kernel(
    const float* __restrict__ Y)
{
    const int tok  = blockIdx.x;
    const int bat  = tok >> 7;
    const int tid  = threadIdx.x;
    const int lane = tid & 31;
    const int warp = tid >> 5;

    __shared__ __align__(16) float2 SV[HDIM];   // (sorted s value, v dual)
    __shared__ __align__(16) float2 TU[HDIM];   // (sorted t value, u dual)
    __shared__ int   sIdx[HDIM];                // sorted pos -> original col
    __shared__ int   tIdx[HDIM];                // sorted pos -> original row
    __shared__ float redA[16], redB[16];        // per-warp dual maxima

    // load
    SV[tid] = make_float2(g_src[tok * HDIM + tid], 0.f);
    TU[tid] = make_float2(Y[tok * HDIM + tid],     0.f);
    sIdx[tid] = tid;
    tIdx[tid] = tid;
    __syncthreads();

    // joint bitonic sort of s-array and t-array (values + index payloads)
    float* svx = &SV[0].x;   // stride-2 float view
    float* tux = &TU[0].x;
    for (int k = 2; k <= HDIM; k <<= 1) {
        for (int j = k >> 1; j > 0; j >>= 1) {
            int ixj = tid ^ j;
            if (ixj > tid) {
                bool up = ((tid & k) == 0);
                float a = svx[2 * tid], b2 = svx[2 * ixj];
                if (up ? (a > b2) : (a < b2)) {
                    svx[2 * tid] = b2; svx[2 * ixj] = a;
                    int ti = sIdx[tid]; sIdx[tid] = sIdx[ixj]; sIdx[ixj] = ti;
                }
                float c = tux[2 * tid], d2 = tux[2 * ixj];
                if (up ? (c > d2) : (c < d2)) {
                    tux[2 * tid] = d2; tux[2 * ixj] = c;
                    int ti = tIdx[tid]; tIdx[tid] = tIdx[ixj]; tIdx[ixj] = ti;
                }
            }
            __syncthreads();
        }
    }

    const float t_own = TU[tid].x;
    const float s_own = SV[tid].x;
    const int   jorig = tIdx[tid];

    // init u via nearest sorted s neighbor: u = -9 + C*d_nn^2
    float u_own;
    {
        int p = lbound(SV, t_own);
        float dn = 3.402823466e+38f;
        if (p < HDIM) dn = fabsf(SV[p].x - t_own);
        if (p > 0)    dn = fminf(dn, fabsf(SV[p - 1].x - t_own));
        u_own = LOGMARG2 + CPOS * dn * dn;
    }
    float v_own = 0.f;
    float V_u = 0.f, V_v = 0.f;   // maxima of current duals

    for (int it = 0; it < NITER; it++) {
        // ---- u-pass (windows over sorted s) ----
        {
            const float sh = u_own + 9.0f;
            const float rad2 = fmaxf((TW + V_v + sh) * INVC, 0.0f);
            const float r = sqrtf(rad2);
            const int lo = lbound(SV, t_own - r);
            const int hi = ubound(SV, t_own + r);
            float a = 1e-30f;
#pragma unroll 2
            for (int c = lo; c < hi; c++) {
                float2 q = SV[c];
                float d = q.x - t_own;
                a += ex2(fmaf(d * d, NEGC, q.y + sh));
            }
            u_own -= lg2(a);
        }
        TU[tid].y = u_own;
        {
            float m = u_own;
#pragma unroll
            for (int o = 16; o; o >>= 1)
                m = fmaxf(m, __shfl_xor_sync(0xffffffffu, m, o));
            if (lane == 0) redA[warp] = m;
        }
        __syncthreads();
        {
            float m = redA[0];
#pragma unroll
            for (int i = 1; i < 16; i++) m = fmaxf(m, redA[i]);
            V_u = m;
        }

        // ---- v-pass (windows over sorted t) ----
        {
            const float sh = v_own + 9.0f;
            const float rad2 = fmaxf((TW + V_u + sh) * INVC, 0.0f);
            const float r = sqrtf(rad2);
            const int lo = lbound(TU, s_own - r);
            const int hi = ubound(TU, s_own + r);
            float a = 1e-30f;
#pragma unroll 2
            for (int c = lo; c < hi; c++) {
                float2 q = TU[c];
                float d = q.x - s_own;
                a += ex2(fmaf(d * d, NEGC, q.y + sh));
            }
            v_own -= lg2(a);
        }
        SV[tid].y = v_own;
        {
            float m = v_own;
#pragma unroll
            for (int o = 16; o; o >>= 1)
                m = fmaxf(m, __shfl_xor_sync(0xffffffffu, m, o));
            if (lane == 0) redB[warp] = m;
        }
        __syncthreads();
        {
            float m = redB[0];
#pragma unroll
            for (int i = 1; i < 16; i++) m = fmaxf(m, redB[i]);
            V_v = m;
        }
    }

    // ---- Plan: P[jorig, iorig] = 2^(tau - 9), tau = -C d^2 + v + u + 9 ----
    {
        float* rowdst = g_sumP + (size_t)bat * HDIM * HDIM + (size_t)jorig * HDIM;
        const float sh = u_own + 9.0f;
        const float rad2 = fmaxf((TW + V_v + sh) * INVC, 0.0f);
        const float r = sqrtf(rad2);
        const int lo = lbound(SV, t_own - r);
        const int hi = ubound(SV, t_own + r);
#pragma unroll 2
        for (int c = lo; c < hi; c++) {
            float2 q = SV[c];
            float d = q.x - t_own;
            float tau = fmaf(d * d, NEGC, q.y + sh);
            // P entry = 2^(tau-9); keep the same 2^-40 cutoff as before
            if (tau > -31.f) atomicAdd(rowdst + sIdx[c], ex2(tau - 9.0f));
        }
    }
}

// ---------------------------------------------------------------------------
// Stage 3: out[tok, k] += sum_{h in slice} src[tok,h]*(sumP[b,h,k]*2000
//                                                      + delta[h,k])
// Grid (16 token-groups of 16, 8 h-slices of 64). 128 CTAs, 256 threads.
// ---------------------------------------------------------------------------
#define OT_TOK 16
#define OT_H   64
__global__ void __launch_bounds__(256) out_kernel(
    const float* __restrict__ delta, float* __restrict__ out)
{
    const int tok0 = blockIdx.x * OT_TOK;
    const int h0   = blockIdx.y * OT_H;
    const int bat  = tok0 >> 7;       // OT_TOK divides SEQ -> no straddle
    const int k2   = threadIdx.x;     // float2 column index (0..255)

    __shared__ float sr[OT_TOK][OT_H];   // 4 KB
    for (int idx = threadIdx.x; idx < OT_TOK * OT_H; idx += 256)
        sr[idx / OT_H][idx % OT_H] = g_src[(tok0 + idx / OT_H) * HDIM + h0 + idx % OT_H];
    __syncthreads();

    const float2* P2 = reinterpret_cast<const float2*>(
        g_sumP + (size_t)bat * HDIM * HDIM);
    const float2* D2 = reinterpret_cast<const float2*>(delta);

    float a0[OT_TOK], a1[OT_TOK];
#pragma unroll
    for (int t = 0; t < OT_TOK; t++) { a0[t] = 0.f; a1[t] = 0.f; }

#pragma unroll 4
    for (int h = 0; h < OT_H; h++) {
        float2 p = __ldg(&P2[(h0 + h) * 256 + k2]);
        float2 d = __ldg(&D2[(h0 + h) * 256 + k2]);
        float pv0 = fmaf(p.x, 2000.0f, d.x);
        float pv1 = fmaf(p.y, 2000.0f, d.y);
#pragma unroll
        for (int t = 0; t < OT_TOK; t++) {
            float s = sr[t][h];
            a0[t] = fmaf(s, pv0, a0[t]);
            a1[t] = fmaf(s, pv1, a1[t]);
        }
    }
#pragma unroll
    for (int t = 0; t < OT_TOK; t++) {
        atomicAdd(&out[(tok0 + t) * HDIM + 2 * k2],     a0[t]);
        atomicAdd(&out[(tok0 + t) * HDIM + 2 * k2 + 1], a1[t]);
    }
}

// ---------------------------------------------------------------------------
extern "C" void kernel_launch(void* const* d_in, const int* in_sizes, int n_in,
                              void* d_out, int out_size)
{
    const float* X     = (const float*)d_in[0];  // (2,128,768)
    const float* Y     = (const float*)d_in[1];  // (2,128,512)
    const float* W     = (const float*)d_in[2];  // (512,768)
    const float* b     = (const float*)d_in[3];  // (512)
    const float* delta = (const float*)d_in[4];  // (512,512)
    float* out = (float*)d_out;                  // (2,128,512)

    zero_kernel<<<(NZ_P + NZ_OUT) / 256, 256>>>(out);
    src_kernel<<<NTOK / TPG, HDIM>>>(X, W, b);
    sinkhorn_kernel<<<NTOK, 512>>>(Y);
    dim3 ogrid(NTOK / OT_TOK, HDIM / OT_H);
    out_kernel<<<ogrid, 256>>>(delta, out);
}

// round 9
// speedup vs baseline: 4.2031x; 2.2561x over previous
#include <cuda_runtime.h>

// Problem constants
#define HDIM   512
#define BATCH  2
#define SEQ    128
#define DSRC   768
#define NTOK   (BATCH * SEQ)   // 256
#define NITER  30
#define NBLK   16              // 512 / 32 sorted blocks

// -(SCALE/REG) * log2(e) = -5000 * 1.4426950408889634
#define NEGC  (-7213.4752044448170f)
#define CPOS  (7213.4752044448170f)
// -log2(H)
#define LOGMARG2 (-9.0f)
// cutoff: drop terms with tau < -TW (mass < 512*2^-60 of a row/col sum)
#define TW 60.0f

// Scratch (static device globals; no runtime allocation allowed)
__device__ float g_src[NTOK * HDIM];            // 512 KB
__device__ float g_sumP[BATCH * HDIM * HDIM];   // 2 MB

__device__ __forceinline__ float ex2(float x) {
    float y; asm("ex2.approx.f32 %0, %1;" : "=f"(y) : "f"(x)); return y;
}
__device__ __forceinline__ float lg2(float x) {
    float y; asm("lg2.approx.f32 %0, %1;" : "=f"(y) : "f"(x)); return y;
}

// ---------------------------------------------------------------------------
// Stage 0: zero plan accumulator AND d_out (harness poisons it; out_kernel
// accumulates with atomics). Graph replays -> must run every launch.
// ---------------------------------------------------------------------------
#define NZ_P   (BATCH * HDIM * HDIM / 4)   // 131072 float4
#define NZ_OUT (NTOK * HDIM / 4)           // 32768 float4
__global__ void zero_kernel(float* __restrict__ out) {
    int i = blockIdx.x * blockDim.x + threadIdx.x;
    float4 z = make_float4(0.f, 0.f, 0.f, 0.f);
    if (i < NZ_P) reinterpret_cast<float4*>(g_sumP)[i] = z;
    else          reinterpret_cast<float4*>(out)[i - NZ_P] = z;
}

// ---------------------------------------------------------------------------
// Stage 1: src[tok, h] = X[tok] . W[h] + b[h]   (4 tokens per CTA)
// ---------------------------------------------------------------------------
#define TPG 4
__global__ void __launch_bounds__(HDIM) src_kernel(
    const float* __restrict__ X, const float* __restrict__ W,
    const float* __restrict__ b)
{
    const int tok0 = blockIdx.x * TPG;
    __shared__ __align__(16) float xs[TPG][DSRC];   // 12 KB
    for (int idx = threadIdx.x; idx < TPG * DSRC; idx += HDIM)
        xs[idx / DSRC][idx % DSRC] = X[tok0 * DSRC + idx];
    __syncthreads();

    const int h = threadIdx.x;
    const float4* wr = reinterpret_cast<const float4*>(W + (size_t)h * DSRC);
    float acc0 = 0.f, acc1 = 0.f, acc2 = 0.f, acc3 = 0.f;
#pragma unroll 4
    for (int q = 0; q < DSRC / 4; q++) {
        float4 w4 = wr[q];
        float4 x0 = reinterpret_cast<const float4*>(xs[0])[q];
        float4 x1 = reinterpret_cast<const float4*>(xs[1])[q];
        float4 x2 = reinterpret_cast<const float4*>(xs[2])[q];
        float4 x3 = reinterpret_cast<const float4*>(xs[3])[q];
        acc0 = fmaf(w4.x, x0.x, acc0); acc0 = fmaf(w4.y, x0.y, acc0);
        acc0 = fmaf(w4.z, x0.z, acc0); acc0 = fmaf(w4.w, x0.w, acc0);
        acc1 = fmaf(w4.x, x1.x, acc1); acc1 = fmaf(w4.y, x1.y, acc1);
        acc1 = fmaf(w4.z, x1.z, acc1); acc1 = fmaf(w4.w, x1.w, acc1);
        acc2 = fmaf(w4.x, x2.x, acc2); acc2 = fmaf(w4.y, x2.y, acc2);
        acc2 = fmaf(w4.z, x2.z, acc2); acc2 = fmaf(w4.w, x2.w, acc2);
        acc3 = fmaf(w4.x, x3.x, acc3); acc3 = fmaf(w4.y, x3.y, acc3);
        acc3 = fmaf(w4.z, x3.z, acc3); acc3 = fmaf(w4.w, x3.w, acc3);
    }
    float bh = b[h];
    g_src[(tok0 + 0) * HDIM + h] = acc0 + bh;
    g_src[(tok0 + 1) * HDIM + h] = acc1 + bh;
    g_src[(tok0 + 2) * HDIM + h] = acc2 + bh;
    g_src[(tok0 + 3) * HDIM + h] = acc3 + bh;
}

// ---------------------------------------------------------------------------
// Binary search over sorted .x of a float2 array (for u-init only).
// ---------------------------------------------------------------------------
__device__ __forceinline__ int lbound(const float2* __restrict__ A, float x) {
    int lo = 0, hi = HDIM;
    while (lo < hi) { int m = (lo + hi) >> 1; if (A[m].x < x) lo = m + 1; else hi = m; }
    return lo;
}

// ---------------------------------------------------------------------------
// One culled half-pass sum: a = sum over qualifying elements of
//   2^( NEGC*(arr[c].x - own)^2 + arr[c].y + sh )
// Blocks of 32 sorted elements are skipped when even their best case
// ( max dual in block, closest boundary distance ) stays below -TW.
// ---------------------------------------------------------------------------
__device__ __forceinline__ float culled_sum(const float2* __restrict__ arr,
                                            const float* __restrict__ blkMax,
                                            float own, float sh)
{
    float a = 1e-30f;
#pragma unroll 1
    for (int b = 0; b < NBLK; b++) {
        float lo = arr[32 * b].x;
        float hi = arr[32 * b + 31].x;
        float dd = fmaxf(fmaxf(lo - own, own - hi), 0.0f);
        if (fmaf(dd * dd, NEGC, blkMax[b] + sh) >= -TW) {
            float aa = 0.f, ab = 0.f;
#pragma unroll
            for (int c = 32 * b; c < 32 * b + 32; c += 2) {
                float2 q0 = arr[c];
                float2 q1 = arr[c + 1];
                float d0 = q0.x - own;
                float d1 = q1.x - own;
                aa += ex2(fmaf(d0 * d0, NEGC, q0.y + sh));
                ab += ex2(fmaf(d1 * d1, NEGC, q1.y + sh));
            }
            a += aa + ab;
        }
    }
    return a;
}

// ---------------------------------------------------------------------------
// Stage 2: block-culled per-token base-2 log-domain Sinkhorn.
// s,t bitonic-sorted with index payloads. Thread tid owns sorted row tid
// (t side, dual u) and sorted column tid (s side, dual v). Warp w == sorted
// block w; after each half-pass it publishes blkMax (max dual in block).
// Half-pass: own_dual -= lg2( culled_sum ), the shifted-LSE update (exact:
// shift = own_dual + 9 keeps all terms <= 0 after the first normalization;
// u-init from the nearest neighbor guarantees it at iteration 0 too).
// ---------------------------------------------------------------------------
__global__ void __launch_bounds__(512, 2) sinkhorn_kernel(
    const float* __restrict__ Y)
{
    const int tok  = blockIdx.x;
    const int bat  = tok >> 7;
    const int tid  = threadIdx.x;
    const int lane = tid & 31;
    const int warp = tid >> 5;

    __shared__ __align__(16) float2 SV[HDIM];   // (sorted s value, v dual)
    __shared__ __align__(16) float2 TU[HDIM];   // (sorted t value, u dual)
    __shared__ int   sIdx[HDIM];                // sorted pos -> original col
    __shared__ int   tIdx[HDIM];                // sorted pos -> original row
    __shared__ float blkMaxV[NBLK];             // per-block max of v (s side)
    __shared__ float blkMaxU[NBLK];             // per-block max of u (t side)

    SV[tid] = make_float2(g_src[tok * HDIM + tid], 0.f);
    TU[tid] = make_float2(Y[tok * HDIM + tid],     0.f);
    sIdx[tid] = tid;
    tIdx[tid] = tid;
    if (tid < NBLK) blkMaxV[tid] = 0.f;
    __syncthreads();

    // joint bitonic sort of s-array and t-array (values + index payloads)
    float* svx = &SV[0].x;
    float* tux = &TU[0].x;
    for (int k = 2; k <= HDIM; k <<= 1) {
        for (int j = k >> 1; j > 0; j >>= 1) {
            int ixj = tid ^ j;
            if (ixj > tid) {
                bool up = ((tid & k) == 0);
                float a = svx[2 * tid], b2 = svx[2 * ixj];
                if (up ? (a > b2) : (a < b2)) {
                    svx[2 * tid] = b2; svx[2 * ixj] = a;
                    int ti = sIdx[tid]; sIdx[tid] = sIdx[ixj]; sIdx[ixj] = ti;
                }
                float c = tux[2 * tid], d2 = tux[2 * ixj];
                if (up ? (c > d2) : (c < d2)) {
                    tux[2 * tid] = d2; tux[2 * ixj] = c;
                    int ti = tIdx[tid]; tIdx[tid] = tIdx[ixj]; tIdx[ixj] = ti;
                }
            }
            __syncthreads();
        }
    }

    const float t_own = TU[tid].x;
    const float s_own = SV[tid].x;
    const int   jorig = tIdx[tid];

    // init u via nearest sorted s neighbor: u = -9 + C*d_nn^2
    float u_own;
    {
        int p = lbound(SV, t_own);
        float dn = 3.402823466e+38f;
        if (p < HDIM) dn = fabsf(SV[p].x - t_own);
        if (p > 0)    dn = fminf(dn, fabsf(SV[p - 1].x - t_own));
        u_own = LOGMARG2 + CPOS * dn * dn;
    }
    float v_own = 0.f;

    for (int it = 0; it < NITER; it++) {
        // ---- u-pass: culled sum over sorted s blocks ----
        u_own -= lg2(culled_sum(SV, blkMaxV, t_own, u_own + 9.0f));
        TU[tid].y = u_own;
        {
            float m = u_own;
#pragma unroll
            for (int o = 16; o; o >>= 1)
                m = fmaxf(m, __shfl_xor_sync(0xffffffffu, m, o));
            if (lane == 0) blkMaxU[warp] = m;
        }
        __syncthreads();

        // ---- v-pass: culled sum over sorted t blocks ----
        v_own -= lg2(culled_sum(TU, blkMaxU, s_own, v_own + 9.0f));
        SV[tid].y = v_own;
        {
            float m = v_own;
#pragma unroll
            for (int o = 16; o; o >>= 1)
                m = fmaxf(m, __shfl_xor_sync(0xffffffffu, m, o));
            if (lane == 0) blkMaxV[warp] = m;
        }
        __syncthreads();
    }

    // ---- Plan: P[jorig, iorig] = 2^(tau - 9), tau = -C d^2 + v + u + 9 ----
    {
        float* rowdst = g_sumP + (size_t)bat * HDIM * HDIM + (size_t)jorig * HDIM;
        const float sh = u_own + 9.0f;
#pragma unroll 1
        for (int b = 0; b < NBLK; b++) {
            float lo = SV[32 * b].x;
            float hi = SV[32 * b + 31].x;
            float dd = fmaxf(fmaxf(lo - t_own, t_own - hi), 0.0f);
            if (fmaf(dd * dd, NEGC, blkMaxV[b] + sh) >= -31.0f) {
#pragma unroll 4
                for (int c = 32 * b; c < 32 * b + 32; c++) {
                    float2 q = SV[c];
                    float d = q.x - t_own;
                    float tau = fmaf(d * d, NEGC, q.y + sh);
                    if (tau > -31.f) atomicAdd(rowdst + sIdx[c], ex2(tau - 9.0f));
                }
            }
        }
    }
}

// ---------------------------------------------------------------------------
// Stage 3: out[tok, k] += sum_{h in slice} src[tok,h]*(sumP[b,h,k]*2000
//                                                      + delta[h,k])
// Grid (16 token-groups of 16, 8 h-slices of 64). 128 CTAs, 256 threads.
// ---------------------------------------------------------------------------
#define OT_TOK 16
#define OT_H   64
__global__ void __launch_bounds__(256) out_kernel(
    const float* __restrict__ delta, float* __restrict__ out)
{
    const int tok0 = blockIdx.x * OT_TOK;
    const int h0   = blockIdx.y * OT_H;
    const int bat  = tok0 >> 7;       // OT_TOK divides SEQ -> no straddle
    const int k2   = threadIdx.x;     // float2 column index (0..255)

    __shared__ float sr[OT_TOK][OT_H];   // 4 KB
    for (int idx = threadIdx.x; idx < OT_TOK * OT_H; idx += 256)
        sr[idx / OT_H][idx % OT_H] = g_src[(tok0 + idx / OT_H) * HDIM + h0 + idx % OT_H];
    __syncthreads();

    const float2* P2 = reinterpret_cast<const float2*>(
        g_sumP + (size_t)bat * HDIM * HDIM);
    const float2* D2 = reinterpret_cast<const float2*>(delta);

    float a0[OT_TOK], a1[OT_TOK];
#pragma unroll
    for (int t = 0; t < OT_TOK; t++) { a0[t] = 0.f; a1[t] = 0.f; }

#pragma unroll 4
    for (int h = 0; h < OT_H; h++) {
        float2 p = __ldg(&P2[(h0 + h) * 256 + k2]);
        float2 d = __ldg(&D2[(h0 + h) * 256 + k2]);
        float pv0 = fmaf(p.x, 2000.0f, d.x);
        float pv1 = fmaf(p.y, 2000.0f, d.y);
#pragma unroll
        for (int t = 0; t < OT_TOK; t++) {
            float s = sr[t][h];
            a0[t] = fmaf(s, pv0, a0[t]);
            a1[t] = fmaf(s, pv1, a1[t]);
        }
    }
#pragma unroll
    for (int t = 0; t < OT_TOK; t++) {
        atomicAdd(&out[(tok0 + t) * HDIM + 2 * k2],     a0[t]);
        atomicAdd(&out[(tok0 + t) * HDIM + 2 * k2 + 1], a1[t]);
    }
}

// ---------------------------------------------------------------------------
extern "C" void kernel_launch(void* const* d_in, const int* in_sizes, int n_in,
                              void* d_out, int out_size)
{
    const float* X     = (const float*)d_in[0];  // (2,128,768)
    const float* Y     = (const float*)d_in[1];  // (2,128,512)
    const float* W     = (const float*)d_in[2];  // (512,768)
    const float* b     = (const float*)d_in[3];  // (512)
    const float* delta = (const float*)d_in[4];  // (512,512)
    float* out = (float*)d_out;                  // (2,128,512)

    zero_kernel<<<(NZ_P + NZ_OUT) / 256, 256>>>(out);
    src_kernel<<<NTOK / TPG, HDIM>>>(X, W, b);
    sinkhorn_kernel<<<NTOK, 512>>>(Y);
    dim3 ogrid(NTOK / OT_TOK, HDIM / OT_H);
    out_kernel<<<ogrid, 256>>>(delta, out);
}